// round 16
// baseline (speedup 1.0000x reference)
#include <cuda_runtime.h>
#include <cuda_bf16.h>
#include <math.h>

#define BB 32
#define LL 1024
#define EMB 128
#define HH 384
#define NLAYER 4
#define NVOCAB 100
#define G4 (4*HH)
#define MM (BB*LL)
#define CTXIN 300
#define HB (HH*BB)
#define NWCTA 128          // wavefront CTAs (32 per layer)
#define P2A 36             // A smem pitch (uint2): 36%16==4 -> conflict-free LDS.64
#define P2B 52             // B smem pitch (uint2): 52%16==4 -> conflict-free LDS.64

// ---------------- static scratch ----------------
__device__ float g_x0[MM * 2 * EMB];
__device__ float g_seqB[MM * HH];               // Y3 [B,L,H]
__device__ uint2 g_x0p[(size_t)LL * 128 * BB];  // packed split-bf16 x0 [t][kp][b]
__device__ float g_keys[MM * HH];
__device__ float g_scores[(size_t)BB * LL * LL];
__device__ float g_cat[MM * 2 * HH];
__device__ float g_comb[MM * HH];
__device__ uint2 g_hSp[2 * NLAYER * 192 * BB];  // packed split-bf16 state [par][l][kp][b]
__device__ unsigned g_barCount;

// ---------------- barrier helpers ----------------
__device__ __forceinline__ void bar_arrive_release(unsigned* p) {
    asm volatile("red.release.gpu.add.u32 [%0], %1;" :: "l"(p), "r"(1u) : "memory");
}
__device__ __forceinline__ unsigned ld_acquire(unsigned* p) {
    unsigned v;
    asm volatile("ld.acquire.gpu.u32 %0, [%1];" : "=r"(v) : "l"(p) : "memory");
    return v;
}

// ---------------- bf16 split helpers ----------------
__device__ __forceinline__ unsigned pkbf2(float lo_val, float hi_val) {
    unsigned r;
    asm("cvt.rn.bf16x2.f32 %0, %1, %2;" : "=r"(r) : "f"(hi_val), "f"(lo_val));
    return r;
}
__device__ __forceinline__ float bfhi(float x) {
    return __bfloat162float(__float2bfloat16_rn(x));
}
__device__ __forceinline__ void mma16(float* c, const unsigned* a, const unsigned* b) {
    asm volatile(
        "mma.sync.aligned.m16n8k16.row.col.f32.bf16.bf16.f32 "
        "{%0,%1,%2,%3}, {%4,%5,%6,%7}, {%8,%9}, {%0,%1,%2,%3};"
        : "+f"(c[0]), "+f"(c[1]), "+f"(c[2]), "+f"(c[3])
        : "r"(a[0]), "r"(a[1]), "r"(a[2]), "r"(a[3]), "r"(b[0]), "r"(b[1]));
}

// ---------------- tensor-core GEMM (3-pass split-bf16) ----------------
#define SPB 136
__global__ __launch_bounds__(256)
void gemm_tc(const float* __restrict__ A, int lda,
             const float* __restrict__ W, int ldw,
             const float* __restrict__ b1, const float* __restrict__ b2,
             float* __restrict__ C, int ldc,
             int M, int N, int K,
             float scale, int act, int causal, int causalK, int trans,
             size_t sA, size_t sW, size_t sC)
{
    int m0 = blockIdx.y * 128;
    int n0 = blockIdx.x * 128;
    if (causal && n0 > m0 + 127) return;
    A += (size_t)blockIdx.z * sA;
    W += (size_t)blockIdx.z * sW;
    C += (size_t)blockIdx.z * sC;
    int Klim = causalK ? min(K, m0 + 128) : K;

    __shared__ unsigned As_hi[8 * SPB], As_lo[8 * SPB];
    __shared__ unsigned Bs_hi[8 * SPB], Bs_lo[8 * SPB];

    const int tid = threadIdx.x;
    const int lr = tid >> 1, lq = tid & 1;
    const int pB = tid >> 5, nq = (tid & 31) * 4;
    const int lane = tid & 31;
    const int g = lane >> 2, tg = lane & 3;
    const int wid = tid >> 5;
    const int mBase = (wid & 3) * 32;
    const int nBase = (wid >> 2) * 64;

    float acc[2][8][4];
#pragma unroll
    for (int mt = 0; mt < 2; mt++)
#pragma unroll
        for (int nt = 0; nt < 8; nt++)
#pragma unroll
            for (int i = 0; i < 4; i++) acc[mt][nt][i] = 0.f;

    float4 a4[2], b4[2];

#define LOAD_TILE(K0)                                                          \
    {                                                                          \
        int k0_ = (K0);                                                        \
        const float* ap = A + (size_t)(m0 + lr) * lda;                         \
        _Pragma("unroll")                                                      \
        for (int j = 0; j < 2; j++) {                                          \
            int kb = k0_ + lq * 8 + j * 4;                                     \
            float4 v = make_float4(0.f, 0.f, 0.f, 0.f);                        \
            if (kb + 3 < Klim) v = *(const float4*)(ap + kb);                  \
            else {                                                             \
                if (kb + 0 < Klim) v.x = ap[kb + 0];                           \
                if (kb + 1 < Klim) v.y = ap[kb + 1];                           \
                if (kb + 2 < Klim) v.z = ap[kb + 2];                           \
            }                                                                  \
            a4[j] = v;                                                         \
        }                                                                      \
        if (trans) {                                                           \
            int wr = n0 + lr;                                                  \
            const float* wp = W + (size_t)wr * ldw;                            \
            _Pragma("unroll")                                                  \
            for (int j = 0; j < 2; j++) {                                      \
                int kb = k0_ + lq * 8 + j * 4;                                 \
                float4 v = make_float4(0.f, 0.f, 0.f, 0.f);                    \
                if (wr < N) {                                                  \
                    if (kb + 3 < Klim) v = *(const float4*)(wp + kb);          \
                    else {                                                     \
                        if (kb + 0 < Klim) v.x = wp[kb + 0];                   \
                        if (kb + 1 < Klim) v.y = wp[kb + 1];                   \
                        if (kb + 2 < Klim) v.z = wp[kb + 2];                   \
                    }                                                          \
                }                                                              \
                b4[j] = v;                                                     \
            }                                                                  \
        } else {                                                               \
            int kk0 = k0_ + 2 * pB;                                            \
            int kk1 = kk0 + 1;                                                 \
            b4[0] = (kk0 < Klim)                                               \
                  ? *(const float4*)(W + (size_t)kk0 * ldw + n0 + nq)          \
                  : make_float4(0.f, 0.f, 0.f, 0.f);                           \
            b4[1] = (kk1 < Klim)                                               \
                  ? *(const float4*)(W + (size_t)kk1 * ldw + n0 + nq)          \
                  : make_float4(0.f, 0.f, 0.f, 0.f);                           \
        }                                                                      \
    }

    LOAD_TILE(0);

    for (int k0 = 0; k0 < Klim; k0 += 16) {
#pragma unroll
        for (int j = 0; j < 2; j++) {
            float4 e = a4[j];
            int kp = lq * 4 + j * 2;
            float hx = bfhi(e.x), hy = bfhi(e.y), hz = bfhi(e.z), hw = bfhi(e.w);
            As_hi[kp * SPB + lr]       = pkbf2(hx, hy);
            As_hi[(kp + 1) * SPB + lr] = pkbf2(hz, hw);
            As_lo[kp * SPB + lr]       = pkbf2(e.x - hx, e.y - hy);
            As_lo[(kp + 1) * SPB + lr] = pkbf2(e.z - hz, e.w - hw);
        }
        if (trans) {
#pragma unroll
            for (int j = 0; j < 2; j++) {
                float4 e = b4[j];
                int kp = lq * 4 + j * 2;
                float hx = bfhi(e.x), hy = bfhi(e.y), hz = bfhi(e.z), hw = bfhi(e.w);
                Bs_hi[kp * SPB + lr]       = pkbf2(hx, hy);
                Bs_hi[(kp + 1) * SPB + lr] = pkbf2(hz, hw);
                Bs_lo[kp * SPB + lr]       = pkbf2(e.x - hx, e.y - hy);
                Bs_lo[(kp + 1) * SPB + lr] = pkbf2(e.z - hz, e.w - hw);
            }
        } else {
            const float* r0 = &b4[0].x;
            const float* r1 = &b4[1].x;
            unsigned hi4[4], lo4[4];
#pragma unroll
            for (int i = 0; i < 4; i++) {
                float h0 = bfhi(r0[i]), h1 = bfhi(r1[i]);
                hi4[i] = pkbf2(h0, h1);
                lo4[i] = pkbf2(r0[i] - h0, r1[i] - h1);
            }
            *(uint4*)(Bs_hi + pB * SPB + nq) = make_uint4(hi4[0], hi4[1], hi4[2], hi4[3]);
            *(uint4*)(Bs_lo + pB * SPB + nq) = make_uint4(lo4[0], lo4[1], lo4[2], lo4[3]);
        }
        __syncthreads();

        if (k0 + 16 < Klim) LOAD_TILE(k0 + 16);

        unsigned ah[2][4], al[2][4];
#pragma unroll
        for (int mt = 0; mt < 2; mt++) {
            int m = mBase + mt * 16 + g;
            ah[mt][0] = As_hi[tg * SPB + m];
            ah[mt][1] = As_hi[tg * SPB + m + 8];
            ah[mt][2] = As_hi[(tg + 4) * SPB + m];
            ah[mt][3] = As_hi[(tg + 4) * SPB + m + 8];
            al[mt][0] = As_lo[tg * SPB + m];
            al[mt][1] = As_lo[tg * SPB + m + 8];
            al[mt][2] = As_lo[(tg + 4) * SPB + m];
            al[mt][3] = As_lo[(tg + 4) * SPB + m + 8];
        }
#pragma unroll
        for (int nt = 0; nt < 8; nt++) {
            int n = nBase + nt * 8 + g;
            unsigned bh[2], bl[2];
            bh[0] = Bs_hi[tg * SPB + n];
            bh[1] = Bs_hi[(tg + 4) * SPB + n];
            bl[0] = Bs_lo[tg * SPB + n];
            bl[1] = Bs_lo[(tg + 4) * SPB + n];
#pragma unroll
            for (int mt = 0; mt < 2; mt++) {
                mma16(acc[mt][nt], ah[mt], bh);
                mma16(acc[mt][nt], ah[mt], bl);
                mma16(acc[mt][nt], al[mt], bh);
            }
        }
        __syncthreads();
    }

#pragma unroll
    for (int mt = 0; mt < 2; mt++) {
        int row0 = m0 + mBase + mt * 16 + g;
        int row1 = row0 + 8;
#pragma unroll
        for (int nt = 0; nt < 8; nt++) {
            int col = n0 + nBase + nt * 8 + 2 * tg;
            float bias = 0.f, bias1 = 0.f;
            if (col < N) { if (b1) bias += b1[col]; if (b2) bias += b2[col]; }
            if (col + 1 < N) { if (b1) bias1 += b1[col + 1]; if (b2) bias1 += b2[col + 1]; }
            float v0 = acc[mt][nt][0] * scale + bias;
            float v1 = acc[mt][nt][1] * scale + bias1;
            float v2 = acc[mt][nt][2] * scale + bias;
            float v3 = acc[mt][nt][3] * scale + bias1;
            if (act) { v0 = tanhf(v0); v1 = tanhf(v1); v2 = tanhf(v2); v3 = tanhf(v3); }
            if (col + 1 < N) {
                *(float2*)(C + (size_t)row0 * ldc + col) = make_float2(v0, v1);
                *(float2*)(C + (size_t)row1 * ldc + col) = make_float2(v2, v3);
            } else if (col < N) {
                C[(size_t)row0 * ldc + col] = v0;
                C[(size_t)row1 * ldc + col] = v2;
            }
        }
    }
}

// ---------------- embedding gather ----------------
__global__ void embed_kernel(const int* __restrict__ x, const float* __restrict__ emb,
                             float* __restrict__ X0)
{
    int i = blockIdx.x * 256 + threadIdx.x;
    if (i >= MM * EMB) return;
    int m = i >> 7, e = i & 127;
    X0[(size_t)m * 256 + e] = emb[(size_t)x[m] * EMB + e];
}

// ---------------- pack x0 [b*L+t][256] -> packed split-bf16 [t][128kp][32b] --
__global__ __launch_bounds__(1024)
void pack_x0(const float* __restrict__ x0, uint2* __restrict__ xp)
{
    __shared__ float tile[32][257];
    int t = blockIdx.x;
    int b = threadIdx.y;
#pragma unroll
    for (int j = 0; j < 8; j++) {
        int k = j * 32 + threadIdx.x;
        tile[b][k] = x0[((size_t)b * LL + t) * 256 + k];
    }
    __syncthreads();
    int id = threadIdx.y * 32 + threadIdx.x;
#pragma unroll
    for (int j = 0; j < 4; j++) {
        int e = id + j * 1024;          // 0..4095
        int kp = e >> 5, bb = e & 31;
        float w0 = tile[bb][2 * kp], w1 = tile[bb][2 * kp + 1];
        float h0 = bfhi(w0), h1 = bfhi(w1);
        xp[((size_t)t * 128 + kp) * BB + bb] =
            make_uint2(pkbf2(h0, h1), pkbf2(w0 - h0, w1 - h1));
    }
}

// ---------------- wavefront state init: h_in [l][b][k] -> packed hSp -------
__global__ void init_wave_state(const float* __restrict__ h_in, uint2* __restrict__ hSp)
{
    int i = blockIdx.x * 256 + threadIdx.x;
    if (i >= NLAYER * 192 * BB) return;
    int l = i / (192 * BB), rem = i - l * (192 * BB);
    int kp = rem >> 5, b = rem & 31;
    float h0 = h_in[l * HB + b * HH + 2 * kp];
    float h1 = h_in[l * HB + b * HH + 2 * kp + 1];
    float e0 = bfhi(h0), e1 = bfhi(h1);
    hSp[((size_t)((l + 1) & 1) * NLAYER + l) * (192 * BB) + kp * BB + b] =
        make_uint2(pkbf2(e0, e1), pkbf2(h0 - e0, h1 - e1));
}

// ---------------- tensor-core wavefront LSTM: 4 layers, 1027 slots ----------
// 128 CTAs x 128 thr. Layer-0 input projection fused in-loop (x packed in xp).
// smem: weights uint2[384][52] (l0 uses 320 rows), A stage uint2[192][36].
__global__ __launch_bounds__(128, 1)
void lstm_wave(const uint2* __restrict__ xp,     // [t][128][32] packed x0
               const float* __restrict__ Whh,    // [4][1536][384]
               const float* __restrict__ Wih0,   // [1536][256]
               const float* __restrict__ WihR,   // [3][1536][384]
               const float* __restrict__ bih, const float* __restrict__ bhh,
               const float* __restrict__ c0,     // [4][B][H]
               float* __restrict__ Y3,           // [B][L][H]
               uint2* __restrict__ hSp,          // [2][4][192][32] packed
               float* __restrict__ outh, float* __restrict__ outc,
               int writeState)
{
    extern __shared__ uint2 sm2[];
    uint2* Bw  = sm2;                   // [384 kp][P2B]
    uint2* Asm = sm2 + 384 * P2B;       // [192 kp][P2A]

    const int tid  = threadIdx.x;
    const int wid  = tid >> 5;
    const int lane = tid & 31;
    const int g  = lane >> 2, tg = lane & 3;
    const int l   = blockIdx.x >> 5;
    const int sub = blockIdx.x & 31;
    const int mt16   = (wid & 1) * 16;
    const int ntBase = (wid >> 1) * 3;

    // ---- convert weights to packed split-bf16 smem (once) ----
    const float* Whh_l = Whh + (size_t)l * G4 * HH;
    const float* Wih_l = (l > 0) ? (WihR + (size_t)(l - 1) * G4 * HH) : WihR;
    const int kpMax = (l == 0) ? 320 : 384;
    for (int e = tid; e < 48 * 384; e += 128) {
        int kp = e / 48, c = e - kp * 48;
        if (kp < kpMax) {
            int row = sub * 12 + (c >> 2) + (c & 3) * HH;
            float w0, w1;
            if (kp < 192) {
                w0 = Whh_l[(size_t)row * HH + 2 * kp];
                w1 = Whh_l[(size_t)row * HH + 2 * kp + 1];
            } else if (l == 0) {
                w0 = Wih0[(size_t)row * 256 + 2 * (kp - 192)];
                w1 = Wih0[(size_t)row * 256 + 2 * (kp - 192) + 1];
            } else {
                w0 = Wih_l[(size_t)row * HH + 2 * (kp - 192)];
                w1 = Wih_l[(size_t)row * HH + 2 * (kp - 192) + 1];
            }
            float h0 = bfhi(w0), h1 = bfhi(w1);
            Bw[kp * P2B + c] = make_uint2(pkbf2(h0, h1), pkbf2(w0 - h0, w1 - h1));
        }
    }

    // ---- per-thread cells (3): warp-fixed mt, nt = ntBase + i ----
    int bc[3], jgg[3];
    float c_r[3], h_r[3];
    float bi[3][4];
#pragma unroll
    for (int i = 0; i < 3; i++) {
        bc[i]  = mt16 + g + 8 * (tg & 1);
        jgg[i] = sub * 12 + 2 * (ntBase + i) + (tg >> 1);
        c_r[i] = c0[l * HB + bc[i] * HH + jgg[i]];
        h_r[i] = 0.f;
#pragma unroll
        for (int q = 0; q < 4; q++)
            bi[i][q] = bih[l * G4 + q * HH + jgg[i]] + bhh[l * G4 + q * HH + jgg[i]];
    }

    const int NS = LL + NLAYER - 1;
    for (int s = 0; s < NS; s++) {
        int t = s - l;
        bool active = (t >= 0) && (t < LL);

        // ---- grid barrier ----
        __syncthreads();
        if (tid == 0) {
            bar_arrive_release(&g_barCount);
            unsigned tgt = (unsigned)NWCTA * (unsigned)(s + 1);
            while (ld_acquire(&g_barCount) < tgt) {}
        }
        __syncthreads();
        if (!active) continue;

        const uint2* hsrcP = hSp + ((size_t)((s + 1) & 1) * NLAYER + l) * (192 * BB);
        const uint2* xsrcP = (l == 0)
            ? (xp + (size_t)t * 128 * BB)
            : (hSp + ((size_t)((s + 1) & 1) * NLAYER + (l - 1)) * (192 * BB));

        float acc[3][4];
#pragma unroll
        for (int i = 0; i < 3; i++)
#pragma unroll
            for (int q = 0; q < 4; q++) acc[i][q] = 0.f;

        for (int ph = 0; ph < 2; ph++) {
            // ---- stage packed A: pure copy, no conversion ----
            const uint4* src4 = (const uint4*)(ph ? xsrcP : hsrcP);
            const int nStage = (ph && l == 0) ? 16 : 24;
            for (int it = 0; it < nStage; it++) {
                int idx = tid + it * 128;          // uint4 index
                int kp = idx >> 4, bp = idx & 15;  // uint4 covers b = 2bp, 2bp+1
                uint4 v = __ldcv(src4 + idx);
                *(uint4*)(Asm + kp * P2A + 2 * bp) = v;
            }
            __syncthreads();

            int kpB = ph * 192;
            const int nIt = (ph && l == 0) ? 16 : 24;
            for (int it = 0; it < nIt; it++) {
                int r0 = it * 8 + tg, r1 = r0 + 4;
                const uint2* Ar0 = Asm + r0 * P2A + mt16 + g;
                const uint2* Ar1 = Asm + r1 * P2A + mt16 + g;
                uint2 a0 = Ar0[0], a1 = Ar0[8], a2 = Ar1[0], a3 = Ar1[8];
                unsigned ah[4] = {a0.x, a1.x, a2.x, a3.x};
                unsigned al[4] = {a0.y, a1.y, a2.y, a3.y};
                const uint2* Br0 = Bw + (kpB + r0) * P2B + g;
                const uint2* Br1 = Bw + (kpB + r1) * P2B + g;
#pragma unroll
                for (int i = 0; i < 3; i++) {
                    int co = (ntBase + i) * 8;
                    uint2 b0 = Br0[co], b1 = Br1[co];
                    unsigned bh[2] = {b0.x, b1.x};
                    unsigned bl[2] = {b0.y, b1.y};
                    mma16(acc[i], ah, bh);
                    mma16(acc[i], ah, bl);
                    mma16(acc[i], al, bh);
                }
            }
            if (ph == 0) __syncthreads();   // A-buffer reuse
        }

        // ---- combine gates, activations, pack + write state ----
        uint2* hdst = hSp + ((size_t)(s & 1) * NLAYER + l) * (192 * BB);
#pragma unroll
        for (int i = 0; i < 3; i++) {
            float x_ = (tg & 1) ? acc[i][0] : acc[i][2];
            float y_ = (tg & 1) ? acc[i][1] : acc[i][3];
            float sx = __shfl_xor_sync(0xffffffffu, x_, 1);
            float sy = __shfl_xor_sync(0xffffffffu, y_, 1);
            float gi, gf, gG, gO;
            if ((tg & 1) == 0) { gi = acc[i][0]; gf = acc[i][1]; gG = sx; gO = sy; }
            else               { gi = sx; gf = sy; gG = acc[i][2]; gO = acc[i][3]; }
            gi += bi[i][0]; gf += bi[i][1]; gG += bi[i][2]; gO += bi[i][3];
            float ig = 1.f / (1.f + expf(-gi));
            float fg = 1.f / (1.f + expf(-gf));
            float G  = tanhf(gG);
            float og = 1.f / (1.f + expf(-gO));
            c_r[i] = fg * c_r[i] + ig * G;
            h_r[i] = og * tanhf(c_r[i]);

            // pack (jg even, jg odd) on same b via shfl, even lane stores
            float hpart = __shfl_xor_sync(0xffffffffu, h_r[i], 2);
            if ((tg & 2) == 0) {
                float he = h_r[i];
                float ee = bfhi(he), eo = bfhi(hpart);
                hdst[(jgg[i] >> 1) * BB + bc[i]] =
                    make_uint2(pkbf2(ee, eo), pkbf2(he - ee, hpart - eo));
            }
            if (l == 3) Y3[((size_t)bc[i] * LL + t) * HH + jgg[i]] = h_r[i];
        }
    }

    if (writeState) {
#pragma unroll
        for (int i = 0; i < 3; i++) {
            outh[l * HB + bc[i] * HH + jgg[i]] = h_r[i];
            outc[l * HB + bc[i] * HH + jgg[i]] = c_r[i];
        }
    }
}

// ---------------- causal softmax (exp stored on first pass) ----------------
__global__ __launch_bounds__(256)
void softmax_causal(float* __restrict__ S)
{
    int bq = blockIdx.x;
    int b = bq >> 10, q = bq & 1023;
    float* row = S + ((size_t)b * LL + q) * LL;
    int len = q + 1;
    int tid = threadIdx.x;
    __shared__ float red[256];

    float mx = -1e30f;
    for (int k = tid; k < len; k += 256) mx = fmaxf(mx, row[k]);
    red[tid] = mx; __syncthreads();
    for (int s = 128; s > 0; s >>= 1) {
        if (tid < s) red[tid] = fmaxf(red[tid], red[tid + s]);
        __syncthreads();
    }
    mx = red[0]; __syncthreads();

    float sum = 0.f;
    for (int k = tid; k < len; k += 256) {
        float e = expf(row[k] - mx);
        row[k] = e;
        sum += e;
    }
    red[tid] = sum; __syncthreads();
    for (int s = 128; s > 0; s >>= 1) {
        if (tid < s) red[tid] += red[tid + s];
        __syncthreads();
    }
    sum = red[0]; __syncthreads();

    float inv = 1.f / sum;
    for (int k = tid; k < LL; k += 256)
        row[k] = (k < len) ? row[k] * inv : 0.f;
}

// ---------------- concat [out | ctx] ----------------
__global__ void concat_kernel(const float* __restrict__ Yout, const float* __restrict__ ctx,
                              float* __restrict__ cat)
{
    int i = blockIdx.x * 256 + threadIdx.x;
    if (i >= MM * 2 * HH) return;
    int m = i / (2 * HH), j = i % (2 * HH);
    cat[i] = (j < HH) ? Yout[(size_t)m * HH + j] : ctx[(size_t)m * HH + j - HH];
}

// ---------------- host ----------------
extern "C" void kernel_launch(void* const* d_in, const int* in_sizes, int n_in,
                              void* d_out, int out_size)
{
    const int*   x       = (const int*)d_in[0];
    const float* context = (const float*)d_in[1];
    const float* h_in    = (const float*)d_in[2];
    const float* c_in    = (const float*)d_in[3];
    const float* emb     = (const float*)d_in[4];
    const float* ctx_W   = (const float*)d_in[5];
    const float* ctx_b   = (const float*)d_in[6];
    const float* Wih0    = (const float*)d_in[7];
    const float* WihR    = (const float*)d_in[8];
    const float* Whh     = (const float*)d_in[9];
    const float* bih     = (const float*)d_in[10];
    const float* bhh     = (const float*)d_in[11];
    const float* Wa      = (const float*)d_in[12];
    const float* comb_W  = (const float*)d_in[13];
    const float* comb_b  = (const float*)d_in[14];
    const float* fc_W    = (const float*)d_in[15];
    const float* fc_b    = (const float*)d_in[16];
    float* out = (float*)d_out;

    float *x0, *Y3, *keys, *scores, *cat, *comb;
    uint2 *hSp, *x0p;
    unsigned* barCount;
    cudaGetSymbolAddress((void**)&x0,       g_x0);
    cudaGetSymbolAddress((void**)&Y3,       g_seqB);
    cudaGetSymbolAddress((void**)&x0p,      g_x0p);
    cudaGetSymbolAddress((void**)&keys,     g_keys);
    cudaGetSymbolAddress((void**)&scores,   g_scores);
    cudaGetSymbolAddress((void**)&cat,      g_cat);
    cudaGetSymbolAddress((void**)&comb,     g_comb);
    cudaGetSymbolAddress((void**)&hSp,      g_hSp);
    cudaGetSymbolAddress((void**)&barCount, g_barCount);

    const int waveSmem = (384 * P2B + 192 * P2A) * 8;   // 215,040 B
    cudaFuncSetAttribute(lstm_wave, cudaFuncAttributeMaxDynamicSharedMemorySize, waveSmem);

    const int logitsN = MM * NVOCAB;
    const bool wantState = (out_size >= logitsN + 2 * NLAYER * BB * HH);
    float* outh = out + logitsN;
    float* outc = out + logitsN + NLAYER * BB * HH;

    // 1) embedding + context projection -> x0 [M,256], pack for wave
    embed_kernel<<<(MM * EMB + 255) / 256, 256>>>(x, emb, x0);
    gemm_tc<<<dim3(1, 256, 1), 256>>>(context, CTXIN, ctx_W, CTXIN, ctx_b, nullptr,
                                      x0 + EMB, 2 * EMB, MM, EMB, CTXIN,
                                      1.f, 0, 0, 0, 1, 0, 0, 0);
    pack_x0<<<LL, dim3(32, 32)>>>(x0, x0p);

    // 2) 4-layer tensor wavefront (layer-0 projection fused in-loop)
    init_wave_state<<<(NLAYER * 192 * BB + 255) / 256, 256>>>(h_in, hSp);
    cudaMemsetAsync(barCount, 0, sizeof(unsigned));
    lstm_wave<<<NWCTA, 128, waveSmem>>>(x0p, Whh, Wih0, WihR, bih, bhh, c_in,
                                        Y3, hSp, outh, outc, wantState ? 1 : 0);

    // 3) attention
    gemm_tc<<<dim3(HH / 128, MM / 128, 1), 256>>>(Y3, HH, Wa, HH, nullptr, nullptr,
                                                  keys, HH, MM, HH, HH,
                                                  1.f, 0, 0, 0, 1, 0, 0, 0);
    float invs = 1.f / sqrtf((float)HH);
    gemm_tc<<<dim3(8, 8, 32), 256>>>(Y3, HH, keys, HH, nullptr, nullptr,
                                     scores, LL, LL, LL, HH,
                                     invs, 0, 1, 0, 1,
                                     (size_t)LL * HH, (size_t)LL * HH, (size_t)LL * LL);
    softmax_causal<<<BB * LL, 256>>>(scores);
    gemm_tc<<<dim3(HH / 128, 8, 32), 256>>>(scores, LL, Y3, HH, nullptr, nullptr,
                                            keys, HH, LL, HH, LL,
                                            1.f, 0, 0, 1, 0,
                                            (size_t)LL * LL, (size_t)LL * HH, (size_t)LL * HH);

    // 4) combine + output head
    concat_kernel<<<(MM * 2 * HH + 255) / 256, 256>>>(Y3, keys, cat);
    gemm_tc<<<dim3(HH / 128, MM / 128, 1), 256>>>(cat, 2 * HH, comb_W, 2 * HH,
                                                  comb_b, nullptr, comb, HH,
                                                  MM, HH, 2 * HH,
                                                  1.f, 1, 0, 0, 1, 0, 0, 0);
    gemm_tc<<<dim3(1, MM / 128, 1), 256>>>(comb, HH, fc_W, HH, fc_b, nullptr,
                                           out, NVOCAB, MM, NVOCAB, HH,
                                           1.f, 0, 0, 0, 1, 0, 0, 0);
}

// round 17
// speedup vs baseline: 1.3308x; 1.3308x over previous
#include <cuda_runtime.h>
#include <cuda_bf16.h>
#include <math.h>

#define BB 32
#define LL 1024
#define EMB 128
#define HH 384
#define NLAYER 4
#define NVOCAB 100
#define G4 (4*HH)
#define MM (BB*LL)
#define CTXIN 300
#define HB (HH*BB)
#define NWCTA 128          // wavefront CTAs (32 per layer)
#define P2A 36             // A smem pitch (uint2): 36%16==4 -> conflict-free LDS.64
#define P2B 52             // B smem pitch (uint2): 52%16==4 -> conflict-free LDS.64

// ---------------- static scratch ----------------
__device__ float g_x0[MM * 2 * EMB];
__device__ float g_seqB[MM * HH];               // Y3 [B,L,H]
__device__ uint2 g_x0p[(size_t)LL * 128 * BB];  // packed split-bf16 x0 [t][kp][b]
__device__ float g_keys[MM * HH];
__device__ float g_scores[(size_t)BB * LL * LL];
__device__ float g_cat[MM * 2 * HH];
__device__ float g_comb[MM * HH];
__device__ uint2 g_hSp[2 * NLAYER * 192 * BB];  // packed split-bf16 state [par][l][kp][b]
__device__ unsigned g_barCount;

// ---------------- barrier helpers ----------------
__device__ __forceinline__ void bar_arrive_release(unsigned* p) {
    asm volatile("red.release.gpu.add.u32 [%0], %1;" :: "l"(p), "r"(1u) : "memory");
}
__device__ __forceinline__ unsigned ld_acquire(unsigned* p) {
    unsigned v;
    asm volatile("ld.acquire.gpu.u32 %0, [%1];" : "=r"(v) : "l"(p) : "memory");
    return v;
}

// ---------------- bf16 split helpers ----------------
__device__ __forceinline__ unsigned pkbf2(float lo_val, float hi_val) {
    unsigned r;
    asm("cvt.rn.bf16x2.f32 %0, %1, %2;" : "=r"(r) : "f"(hi_val), "f"(lo_val));
    return r;
}
__device__ __forceinline__ float bfhi(float x) {
    return __bfloat162float(__float2bfloat16_rn(x));
}
__device__ __forceinline__ void mma16(float* c, const unsigned* a, const unsigned* b) {
    asm volatile(
        "mma.sync.aligned.m16n8k16.row.col.f32.bf16.bf16.f32 "
        "{%0,%1,%2,%3}, {%4,%5,%6,%7}, {%8,%9}, {%0,%1,%2,%3};"
        : "+f"(c[0]), "+f"(c[1]), "+f"(c[2]), "+f"(c[3])
        : "r"(a[0]), "r"(a[1]), "r"(a[2]), "r"(a[3]), "r"(b[0]), "r"(b[1]));
}

// ---------------- tensor-core GEMM (3-pass split-bf16) ----------------
#define SPB 136
__global__ __launch_bounds__(256)
void gemm_tc(const float* __restrict__ A, int lda,
             const float* __restrict__ W, int ldw,
             const float* __restrict__ b1, const float* __restrict__ b2,
             float* __restrict__ C, int ldc,
             int M, int N, int K,
             float scale, int act, int causal, int causalK, int trans,
             size_t sA, size_t sW, size_t sC)
{
    int m0 = blockIdx.y * 128;
    int n0 = blockIdx.x * 128;
    if (causal && n0 > m0 + 127) return;
    A += (size_t)blockIdx.z * sA;
    W += (size_t)blockIdx.z * sW;
    C += (size_t)blockIdx.z * sC;
    int Klim = causalK ? min(K, m0 + 128) : K;

    __shared__ unsigned As_hi[8 * SPB], As_lo[8 * SPB];
    __shared__ unsigned Bs_hi[8 * SPB], Bs_lo[8 * SPB];

    const int tid = threadIdx.x;
    const int lr = tid >> 1, lq = tid & 1;
    const int pB = tid >> 5, nq = (tid & 31) * 4;
    const int lane = tid & 31;
    const int g = lane >> 2, tg = lane & 3;
    const int wid = tid >> 5;
    const int mBase = (wid & 3) * 32;
    const int nBase = (wid >> 2) * 64;

    float acc[2][8][4];
#pragma unroll
    for (int mt = 0; mt < 2; mt++)
#pragma unroll
        for (int nt = 0; nt < 8; nt++)
#pragma unroll
            for (int i = 0; i < 4; i++) acc[mt][nt][i] = 0.f;

    float4 a4[2], b4[2];

#define LOAD_TILE(K0)                                                          \
    {                                                                          \
        int k0_ = (K0);                                                        \
        const float* ap = A + (size_t)(m0 + lr) * lda;                         \
        _Pragma("unroll")                                                      \
        for (int j = 0; j < 2; j++) {                                          \
            int kb = k0_ + lq * 8 + j * 4;                                     \
            float4 v = make_float4(0.f, 0.f, 0.f, 0.f);                        \
            if (kb + 3 < Klim) v = *(const float4*)(ap + kb);                  \
            else {                                                             \
                if (kb + 0 < Klim) v.x = ap[kb + 0];                           \
                if (kb + 1 < Klim) v.y = ap[kb + 1];                           \
                if (kb + 2 < Klim) v.z = ap[kb + 2];                           \
            }                                                                  \
            a4[j] = v;                                                         \
        }                                                                      \
        if (trans) {                                                           \
            int wr = n0 + lr;                                                  \
            const float* wp = W + (size_t)wr * ldw;                            \
            _Pragma("unroll")                                                  \
            for (int j = 0; j < 2; j++) {                                      \
                int kb = k0_ + lq * 8 + j * 4;                                 \
                float4 v = make_float4(0.f, 0.f, 0.f, 0.f);                    \
                if (wr < N) {                                                  \
                    if (kb + 3 < Klim) v = *(const float4*)(wp + kb);          \
                    else {                                                     \
                        if (kb + 0 < Klim) v.x = wp[kb + 0];                   \
                        if (kb + 1 < Klim) v.y = wp[kb + 1];                   \
                        if (kb + 2 < Klim) v.z = wp[kb + 2];                   \
                    }                                                          \
                }                                                              \
                b4[j] = v;                                                     \
            }                                                                  \
        } else {                                                               \
            int kk0 = k0_ + 2 * pB;                                            \
            int kk1 = kk0 + 1;                                                 \
            b4[0] = (kk0 < Klim)                                               \
                  ? *(const float4*)(W + (size_t)kk0 * ldw + n0 + nq)          \
                  : make_float4(0.f, 0.f, 0.f, 0.f);                           \
            b4[1] = (kk1 < Klim)                                               \
                  ? *(const float4*)(W + (size_t)kk1 * ldw + n0 + nq)          \
                  : make_float4(0.f, 0.f, 0.f, 0.f);                           \
        }                                                                      \
    }

    LOAD_TILE(0);

    for (int k0 = 0; k0 < Klim; k0 += 16) {
#pragma unroll
        for (int j = 0; j < 2; j++) {
            float4 e = a4[j];
            int kp = lq * 4 + j * 2;
            float hx = bfhi(e.x), hy = bfhi(e.y), hz = bfhi(e.z), hw = bfhi(e.w);
            As_hi[kp * SPB + lr]       = pkbf2(hx, hy);
            As_hi[(kp + 1) * SPB + lr] = pkbf2(hz, hw);
            As_lo[kp * SPB + lr]       = pkbf2(e.x - hx, e.y - hy);
            As_lo[(kp + 1) * SPB + lr] = pkbf2(e.z - hz, e.w - hw);
        }
        if (trans) {
#pragma unroll
            for (int j = 0; j < 2; j++) {
                float4 e = b4[j];
                int kp = lq * 4 + j * 2;
                float hx = bfhi(e.x), hy = bfhi(e.y), hz = bfhi(e.z), hw = bfhi(e.w);
                Bs_hi[kp * SPB + lr]       = pkbf2(hx, hy);
                Bs_hi[(kp + 1) * SPB + lr] = pkbf2(hz, hw);
                Bs_lo[kp * SPB + lr]       = pkbf2(e.x - hx, e.y - hy);
                Bs_lo[(kp + 1) * SPB + lr] = pkbf2(e.z - hz, e.w - hw);
            }
        } else {
            const float* r0 = &b4[0].x;
            const float* r1 = &b4[1].x;
            unsigned hi4[4], lo4[4];
#pragma unroll
            for (int i = 0; i < 4; i++) {
                float h0 = bfhi(r0[i]), h1 = bfhi(r1[i]);
                hi4[i] = pkbf2(h0, h1);
                lo4[i] = pkbf2(r0[i] - h0, r1[i] - h1);
            }
            *(uint4*)(Bs_hi + pB * SPB + nq) = make_uint4(hi4[0], hi4[1], hi4[2], hi4[3]);
            *(uint4*)(Bs_lo + pB * SPB + nq) = make_uint4(lo4[0], lo4[1], lo4[2], lo4[3]);
        }
        __syncthreads();

        if (k0 + 16 < Klim) LOAD_TILE(k0 + 16);

        unsigned ah[2][4], al[2][4];
#pragma unroll
        for (int mt = 0; mt < 2; mt++) {
            int m = mBase + mt * 16 + g;
            ah[mt][0] = As_hi[tg * SPB + m];
            ah[mt][1] = As_hi[tg * SPB + m + 8];
            ah[mt][2] = As_hi[(tg + 4) * SPB + m];
            ah[mt][3] = As_hi[(tg + 4) * SPB + m + 8];
            al[mt][0] = As_lo[tg * SPB + m];
            al[mt][1] = As_lo[tg * SPB + m + 8];
            al[mt][2] = As_lo[(tg + 4) * SPB + m];
            al[mt][3] = As_lo[(tg + 4) * SPB + m + 8];
        }
#pragma unroll
        for (int nt = 0; nt < 8; nt++) {
            int n = nBase + nt * 8 + g;
            unsigned bh[2], bl[2];
            bh[0] = Bs_hi[tg * SPB + n];
            bh[1] = Bs_hi[(tg + 4) * SPB + n];
            bl[0] = Bs_lo[tg * SPB + n];
            bl[1] = Bs_lo[(tg + 4) * SPB + n];
#pragma unroll
            for (int mt = 0; mt < 2; mt++) {
                mma16(acc[mt][nt], ah[mt], bh);
                mma16(acc[mt][nt], ah[mt], bl);
                mma16(acc[mt][nt], al[mt], bh);
            }
        }
        __syncthreads();
    }

#pragma unroll
    for (int mt = 0; mt < 2; mt++) {
        int row0 = m0 + mBase + mt * 16 + g;
        int row1 = row0 + 8;
#pragma unroll
        for (int nt = 0; nt < 8; nt++) {
            int col = n0 + nBase + nt * 8 + 2 * tg;
            float bias = 0.f, bias1 = 0.f;
            if (col < N) { if (b1) bias += b1[col]; if (b2) bias += b2[col]; }
            if (col + 1 < N) { if (b1) bias1 += b1[col + 1]; if (b2) bias1 += b2[col + 1]; }
            float v0 = acc[mt][nt][0] * scale + bias;
            float v1 = acc[mt][nt][1] * scale + bias1;
            float v2 = acc[mt][nt][2] * scale + bias;
            float v3 = acc[mt][nt][3] * scale + bias1;
            if (act) { v0 = tanhf(v0); v1 = tanhf(v1); v2 = tanhf(v2); v3 = tanhf(v3); }
            if (col + 1 < N) {
                *(float2*)(C + (size_t)row0 * ldc + col) = make_float2(v0, v1);
                *(float2*)(C + (size_t)row1 * ldc + col) = make_float2(v2, v3);
            } else if (col < N) {
                C[(size_t)row0 * ldc + col] = v0;
                C[(size_t)row1 * ldc + col] = v2;
            }
        }
    }
}

// ---------------- embedding gather ----------------
__global__ void embed_kernel(const int* __restrict__ x, const float* __restrict__ emb,
                             float* __restrict__ X0)
{
    int i = blockIdx.x * 256 + threadIdx.x;
    if (i >= MM * EMB) return;
    int m = i >> 7, e = i & 127;
    X0[(size_t)m * 256 + e] = emb[(size_t)x[m] * EMB + e];
}

// ---------------- pack x0 [b*L+t][256] -> packed split-bf16 [t][128kp][32b] --
__global__ __launch_bounds__(1024)
void pack_x0(const float* __restrict__ x0, uint2* __restrict__ xp)
{
    __shared__ float tile[32][257];
    int t = blockIdx.x;
    int b = threadIdx.y;
#pragma unroll
    for (int j = 0; j < 8; j++) {
        int k = j * 32 + threadIdx.x;
        tile[b][k] = x0[((size_t)b * LL + t) * 256 + k];
    }
    __syncthreads();
    int id = threadIdx.y * 32 + threadIdx.x;
#pragma unroll
    for (int j = 0; j < 4; j++) {
        int e = id + j * 1024;          // 0..4095
        int kp = e >> 5, bb = e & 31;
        float w0 = tile[bb][2 * kp], w1 = tile[bb][2 * kp + 1];
        float h0 = bfhi(w0), h1 = bfhi(w1);
        xp[((size_t)t * 128 + kp) * BB + bb] =
            make_uint2(pkbf2(h0, h1), pkbf2(w0 - h0, w1 - h1));
    }
}

// ---------------- wavefront state init: h_in [l][b][k] -> packed hSp -------
__global__ void init_wave_state(const float* __restrict__ h_in, uint2* __restrict__ hSp)
{
    int i = blockIdx.x * 256 + threadIdx.x;
    if (i >= NLAYER * 192 * BB) return;
    int l = i / (192 * BB), rem = i - l * (192 * BB);
    int kp = rem >> 5, b = rem & 31;
    float h0 = h_in[l * HB + b * HH + 2 * kp];
    float h1 = h_in[l * HB + b * HH + 2 * kp + 1];
    float e0 = bfhi(h0), e1 = bfhi(h1);
    hSp[((size_t)((l + 1) & 1) * NLAYER + l) * (192 * BB) + kp * BB + b] =
        make_uint2(pkbf2(e0, e1), pkbf2(h0 - e0, h1 - e1));
}

// ---------------- tensor-core wavefront LSTM: 4 layers, 1027 slots ----------
// 128 CTAs x 128 thr. Layer-0 input projection fused in-loop (x packed in xp).
// All staging/mma loops compile-time bounded (front-batched LDG -> high MLP).
__global__ __launch_bounds__(128, 1)
void lstm_wave(const uint2* __restrict__ xp,     // [t][128][32] packed x0
               const float* __restrict__ Whh,    // [4][1536][384]
               const float* __restrict__ Wih0,   // [1536][256]
               const float* __restrict__ WihR,   // [3][1536][384]
               const float* __restrict__ bih, const float* __restrict__ bhh,
               const float* __restrict__ c0,     // [4][B][H]
               float* __restrict__ Y3,           // [B][L][H]
               uint2* __restrict__ hSp,          // [2][4][192][32] packed
               float* __restrict__ outh, float* __restrict__ outc,
               int writeState)
{
    extern __shared__ uint2 sm2[];
    uint2* Bw  = sm2;                   // [384 kp][P2B]
    uint2* Asm = sm2 + 384 * P2B;       // [192 kp][P2A]

    const int tid  = threadIdx.x;
    const int wid  = tid >> 5;
    const int lane = tid & 31;
    const int g  = lane >> 2, tg = lane & 3;
    const int l   = blockIdx.x >> 5;
    const int sub = blockIdx.x & 31;
    const int mt16   = (wid & 1) * 16;
    const int ntBase = (wid >> 1) * 3;

    // ---- convert weights to packed split-bf16 smem (once) ----
    const float* Whh_l = Whh + (size_t)l * G4 * HH;
    const float* Wih_l = (l > 0) ? (WihR + (size_t)(l - 1) * G4 * HH) : WihR;
    const int kpMax = (l == 0) ? 320 : 384;
    for (int e = tid; e < 48 * 384; e += 128) {
        int kp = e / 48, c = e - kp * 48;
        if (kp < kpMax) {
            int row = sub * 12 + (c >> 2) + (c & 3) * HH;
            float w0, w1;
            if (kp < 192) {
                w0 = Whh_l[(size_t)row * HH + 2 * kp];
                w1 = Whh_l[(size_t)row * HH + 2 * kp + 1];
            } else if (l == 0) {
                w0 = Wih0[(size_t)row * 256 + 2 * (kp - 192)];
                w1 = Wih0[(size_t)row * 256 + 2 * (kp - 192) + 1];
            } else {
                w0 = Wih_l[(size_t)row * HH + 2 * (kp - 192)];
                w1 = Wih_l[(size_t)row * HH + 2 * (kp - 192) + 1];
            }
            float h0 = bfhi(w0), h1 = bfhi(w1);
            Bw[kp * P2B + c] = make_uint2(pkbf2(h0, h1), pkbf2(w0 - h0, w1 - h1));
        }
    }

    // ---- per-thread cells (3): warp-fixed mt, nt = ntBase + i ----
    int bc[3], jgg[3];
    float c_r[3], h_r[3];
    float bi[3][4];
#pragma unroll
    for (int i = 0; i < 3; i++) {
        bc[i]  = mt16 + g + 8 * (tg & 1);
        jgg[i] = sub * 12 + 2 * (ntBase + i) + (tg >> 1);
        c_r[i] = c0[l * HB + bc[i] * HH + jgg[i]];
        h_r[i] = 0.f;
#pragma unroll
        for (int q = 0; q < 4; q++)
            bi[i][q] = bih[l * G4 + q * HH + jgg[i]] + bhh[l * G4 + q * HH + jgg[i]];
    }

    // ---- compile-time-bounded staging / mma macros ----
#define STAGE_A(NIT)                                                           \
    {                                                                          \
        _Pragma("unroll")                                                      \
        for (int it = 0; it < (NIT); it++) {                                   \
            int idx = tid + it * 128;                                          \
            int kp = idx >> 4, bp = idx & 15;                                  \
            uint4 v = __ldcv(src4 + idx);                                      \
            *(uint4*)(Asm + kp * P2A + 2 * bp) = v;                            \
        }                                                                      \
    }
#define MMA_PHASE(NIT, KPB)                                                    \
    for (int it = 0; it < (NIT); it++) {                                       \
        int r0 = it * 8 + tg, r1 = r0 + 4;                                     \
        const uint2* Ar0 = Asm + r0 * P2A + mt16 + g;                          \
        const uint2* Ar1 = Asm + r1 * P2A + mt16 + g;                          \
        uint2 a0 = Ar0[0], a1 = Ar0[8], a2 = Ar1[0], a3 = Ar1[8];              \
        unsigned ah[4] = {a0.x, a1.x, a2.x, a3.x};                             \
        unsigned al[4] = {a0.y, a1.y, a2.y, a3.y};                             \
        const uint2* Br0 = Bw + ((KPB) + r0) * P2B + g;                        \
        const uint2* Br1 = Bw + ((KPB) + r1) * P2B + g;                        \
        _Pragma("unroll")                                                      \
        for (int i = 0; i < 3; i++) {                                          \
            int co = (ntBase + i) * 8;                                         \
            uint2 b0 = Br0[co], b1 = Br1[co];                                  \
            unsigned bh[2] = {b0.x, b1.x};                                     \
            unsigned bl[2] = {b0.y, b1.y};                                     \
            mma16(acc[i], ah, bh);                                             \
            mma16(acc[i], ah, bl);                                             \
            mma16(acc[i], al, bh);                                             \
        }                                                                      \
    }

    const int NS = LL + NLAYER - 1;
    for (int s = 0; s < NS; s++) {
        int t = s - l;
        bool active = (t >= 0) && (t < LL);

        // ---- grid barrier ----
        __syncthreads();
        if (tid == 0) {
            bar_arrive_release(&g_barCount);
            unsigned tgt = (unsigned)NWCTA * (unsigned)(s + 1);
            while (ld_acquire(&g_barCount) < tgt) {}
        }
        __syncthreads();
        if (!active) continue;

        const uint2* hsrcP = hSp + ((size_t)((s + 1) & 1) * NLAYER + l) * (192 * BB);
        const uint2* xsrcP = (l == 0)
            ? (xp + (size_t)t * 128 * BB)
            : (hSp + ((size_t)((s + 1) & 1) * NLAYER + (l - 1)) * (192 * BB));

        float acc[3][4];
#pragma unroll
        for (int i = 0; i < 3; i++)
#pragma unroll
            for (int q = 0; q < 4; q++) acc[i][q] = 0.f;

        // ---- phase 0: h @ Whh ----
        {
            const uint4* src4 = (const uint4*)hsrcP;
            STAGE_A(24)
            __syncthreads();
            MMA_PHASE(24, 0)
            __syncthreads();
        }
        // ---- phase 1: x @ Wih ----
        {
            const uint4* src4 = (const uint4*)xsrcP;
            if (l == 0) {
                STAGE_A(16)
                __syncthreads();
                MMA_PHASE(16, 192)
            } else {
                STAGE_A(24)
                __syncthreads();
                MMA_PHASE(24, 192)
            }
        }

        // ---- combine gates, activations, pack + write state ----
        uint2* hdst = hSp + ((size_t)(s & 1) * NLAYER + l) * (192 * BB);
#pragma unroll
        for (int i = 0; i < 3; i++) {
            float x_ = (tg & 1) ? acc[i][0] : acc[i][2];
            float y_ = (tg & 1) ? acc[i][1] : acc[i][3];
            float sx = __shfl_xor_sync(0xffffffffu, x_, 1);
            float sy = __shfl_xor_sync(0xffffffffu, y_, 1);
            float gi, gf, gG, gO;
            if ((tg & 1) == 0) { gi = acc[i][0]; gf = acc[i][1]; gG = sx; gO = sy; }
            else               { gi = sx; gf = sy; gG = acc[i][2]; gO = acc[i][3]; }
            gi += bi[i][0]; gf += bi[i][1]; gG += bi[i][2]; gO += bi[i][3];
            float ig = 1.f / (1.f + expf(-gi));
            float fg = 1.f / (1.f + expf(-gf));
            float G  = tanhf(gG);
            float og = 1.f / (1.f + expf(-gO));
            c_r[i] = fg * c_r[i] + ig * G;
            h_r[i] = og * tanhf(c_r[i]);

            // pack (jg even, jg odd) on same b via shfl, even lane stores
            float hpart = __shfl_xor_sync(0xffffffffu, h_r[i], 2);
            if ((tg & 2) == 0) {
                float he = h_r[i];
                float ee = bfhi(he), eo = bfhi(hpart);
                hdst[(jgg[i] >> 1) * BB + bc[i]] =
                    make_uint2(pkbf2(ee, eo), pkbf2(he - ee, hpart - eo));
            }
            if (l == 3) Y3[((size_t)bc[i] * LL + t) * HH + jgg[i]] = h_r[i];
        }
    }

    if (writeState) {
#pragma unroll
        for (int i = 0; i < 3; i++) {
            outh[l * HB + bc[i] * HH + jgg[i]] = h_r[i];
            outc[l * HB + bc[i] * HH + jgg[i]] = c_r[i];
        }
    }
}

// ---------------- causal softmax (exp stored on first pass) ----------------
__global__ __launch_bounds__(256)
void softmax_causal(float* __restrict__ S)
{
    int bq = blockIdx.x;
    int b = bq >> 10, q = bq & 1023;
    float* row = S + ((size_t)b * LL + q) * LL;
    int len = q + 1;
    int tid = threadIdx.x;
    __shared__ float red[256];

    float mx = -1e30f;
    for (int k = tid; k < len; k += 256) mx = fmaxf(mx, row[k]);
    red[tid] = mx; __syncthreads();
    for (int s = 128; s > 0; s >>= 1) {
        if (tid < s) red[tid] = fmaxf(red[tid], red[tid + s]);
        __syncthreads();
    }
    mx = red[0]; __syncthreads();

    float sum = 0.f;
    for (int k = tid; k < len; k += 256) {
        float e = expf(row[k] - mx);
        row[k] = e;
        sum += e;
    }
    red[tid] = sum; __syncthreads();
    for (int s = 128; s > 0; s >>= 1) {
        if (tid < s) red[tid] += red[tid + s];
        __syncthreads();
    }
    sum = red[0]; __syncthreads();

    float inv = 1.f / sum;
    for (int k = tid; k < LL; k += 256)
        row[k] = (k < len) ? row[k] * inv : 0.f;
}

// ---------------- concat [out | ctx] ----------------
__global__ void concat_kernel(const float* __restrict__ Yout, const float* __restrict__ ctx,
                              float* __restrict__ cat)
{
    int i = blockIdx.x * 256 + threadIdx.x;
    if (i >= MM * 2 * HH) return;
    int m = i / (2 * HH), j = i % (2 * HH);
    cat[i] = (j < HH) ? Yout[(size_t)m * HH + j] : ctx[(size_t)m * HH + j - HH];
}

// ---------------- host ----------------
extern "C" void kernel_launch(void* const* d_in, const int* in_sizes, int n_in,
                              void* d_out, int out_size)
{
    const int*   x       = (const int*)d_in[0];
    const float* context = (const float*)d_in[1];
    const float* h_in    = (const float*)d_in[2];
    const float* c_in    = (const float*)d_in[3];
    const float* emb     = (const float*)d_in[4];
    const float* ctx_W   = (const float*)d_in[5];
    const float* ctx_b   = (const float*)d_in[6];
    const float* Wih0    = (const float*)d_in[7];
    const float* WihR    = (const float*)d_in[8];
    const float* Whh     = (const float*)d_in[9];
    const float* bih     = (const float*)d_in[10];
    const float* bhh     = (const float*)d_in[11];
    const float* Wa      = (const float*)d_in[12];
    const float* comb_W  = (const float*)d_in[13];
    const float* comb_b  = (const float*)d_in[14];
    const float* fc_W    = (const float*)d_in[15];
    const float* fc_b    = (const float*)d_in[16];
    float* out = (float*)d_out;

    float *x0, *Y3, *keys, *scores, *cat, *comb;
    uint2 *hSp, *x0p;
    unsigned* barCount;
    cudaGetSymbolAddress((void**)&x0,       g_x0);
    cudaGetSymbolAddress((void**)&Y3,       g_seqB);
    cudaGetSymbolAddress((void**)&x0p,      g_x0p);
    cudaGetSymbolAddress((void**)&keys,     g_keys);
    cudaGetSymbolAddress((void**)&scores,   g_scores);
    cudaGetSymbolAddress((void**)&cat,      g_cat);
    cudaGetSymbolAddress((void**)&comb,     g_comb);
    cudaGetSymbolAddress((void**)&hSp,      g_hSp);
    cudaGetSymbolAddress((void**)&barCount, g_barCount);

    const int waveSmem = (384 * P2B + 192 * P2A) * 8;   // 215,040 B
    cudaFuncSetAttribute(lstm_wave, cudaFuncAttributeMaxDynamicSharedMemorySize, waveSmem);

    const int logitsN = MM * NVOCAB;
    const bool wantState = (out_size >= logitsN + 2 * NLAYER * BB * HH);
    float* outh = out + logitsN;
    float* outc = out + logitsN + NLAYER * BB * HH;

    // 1) embedding + context projection -> x0 [M,256], pack for wave
    embed_kernel<<<(MM * EMB + 255) / 256, 256>>>(x, emb, x0);
    gemm_tc<<<dim3(1, 256, 1), 256>>>(context, CTXIN, ctx_W, CTXIN, ctx_b, nullptr,
                                      x0 + EMB, 2 * EMB, MM, EMB, CTXIN,
                                      1.f, 0, 0, 0, 1, 0, 0, 0);
    pack_x0<<<LL, dim3(32, 32)>>>(x0, x0p);

    // 2) 4-layer tensor wavefront (layer-0 projection fused in-loop)
    init_wave_state<<<(NLAYER * 192 * BB + 255) / 256, 256>>>(h_in, hSp);
    cudaMemsetAsync(barCount, 0, sizeof(unsigned));
    lstm_wave<<<NWCTA, 128, waveSmem>>>(x0p, Whh, Wih0, WihR, bih, bhh, c_in,
                                        Y3, hSp, outh, outc, wantState ? 1 : 0);

    // 3) attention
    gemm_tc<<<dim3(HH / 128, MM / 128, 1), 256>>>(Y3, HH, Wa, HH, nullptr, nullptr,
                                                  keys, HH, MM, HH, HH,
                                                  1.f, 0, 0, 0, 1, 0, 0, 0);
    float invs = 1.f / sqrtf((float)HH);
    gemm_tc<<<dim3(8, 8, 32), 256>>>(Y3, HH, keys, HH, nullptr, nullptr,
                                     scores, LL, LL, LL, HH,
                                     invs, 0, 1, 0, 1,
                                     (size_t)LL * HH, (size_t)LL * HH, (size_t)LL * LL);
    softmax_causal<<<BB * LL, 256>>>(scores);
    gemm_tc<<<dim3(HH / 128, 8, 32), 256>>>(scores, LL, Y3, HH, nullptr, nullptr,
                                            keys, HH, LL, HH, LL,
                                            1.f, 0, 0, 1, 0,
                                            (size_t)LL * LL, (size_t)LL * HH, (size_t)LL * HH);

    // 4) combine + output head
    concat_kernel<<<(MM * 2 * HH + 255) / 256, 256>>>(Y3, keys, cat);
    gemm_tc<<<dim3(HH / 128, MM / 128, 1), 256>>>(cat, 2 * HH, comb_W, 2 * HH,
                                                  comb_b, nullptr, comb, HH,
                                                  MM, HH, 2 * HH,
                                                  1.f, 1, 0, 0, 1, 0, 0, 0);
    gemm_tc<<<dim3(1, MM / 128, 1), 256>>>(comb, HH, fc_W, HH, fc_b, nullptr,
                                           out, NVOCAB, MM, NVOCAB, HH,
                                           1.f, 0, 0, 0, 1, 0, 0, 0);
}